// round 10
// baseline (speedup 1.0000x reference)
#include <cuda_runtime.h>
#include <cuda_bf16.h>
#include <stdint.h>
#include <math.h>

#define T_TOK 8192
#define DIM 1024
#define NEXP 16
#define INTER 2048
#define NROWS (2*T_TOK)

#define TM 64
#define TN 128
#define TKC 16
#define KW 12          // words per smem row (8 data + 4 pad) — bank-verified

// ---------------- device scratch ----------------
__device__ int   g_cnt[NEXP];
__device__ int   g_rows[NEXP][T_TOK];   // value = 2*token + slot
__device__ float g_wt[NEXP][T_TOK];
__device__ float g_Z1[(size_t)NROWS * INTER];                        // z1 fp32
__device__ __align__(16) uint32_t g_Hh[(size_t)NROWS * (INTER/2)];   // packed bf16 hi
__device__ __align__(16) uint32_t g_Hl[(size_t)NROWS * (INTER/2)];   // packed bf16 lo

#define MMA16816(d, a, b0, b1) \
    asm volatile("mma.sync.aligned.m16n8k16.row.col.f32.bf16.bf16.f32 " \
        "{%0,%1,%2,%3}, {%4,%5,%6,%7}, {%8,%9}, {%0,%1,%2,%3};" \
        : "+f"((d)[0]), "+f"((d)[1]), "+f"((d)[2]), "+f"((d)[3]) \
        : "r"((a)[0]), "r"((a)[1]), "r"((a)[2]), "r"((a)[3]), "r"(b0), "r"(b1))

__device__ __forceinline__ void f2bf_pair(float v0, float v1,
                                          uint32_t& hi, uint32_t& lo) {
    uint32_t h;
    asm("cvt.rn.bf16x2.f32 %0, %1, %2;" : "=r"(h) : "f"(v1), "f"(v0));
    float h0 = __uint_as_float(h << 16);
    float h1 = __uint_as_float(h & 0xffff0000u);
    uint32_t l;
    asm("cvt.rn.bf16x2.f32 %0, %1, %2;" : "=r"(l) : "f"(v1 - h1), "f"(v0 - h0));
    hi = h; lo = l;
}

// ---------------- kernel 0: reset counters + zero output ----------------
__global__ void zero_kernel(float* __restrict__ y) {
    int i = blockIdx.x * blockDim.x + threadIdx.x;
    if (i < NEXP) g_cnt[i] = 0;
    if (i < T_TOK * DIM / 4) {
        float4 z = make_float4(0.f, 0.f, 0.f, 0.f);
        reinterpret_cast<float4*>(y)[i] = z;
    }
}

// ---------------- kernel 1: gate (unchanged, passing) ----------------
__global__ void gate_kernel(const float* __restrict__ x,
                            const float* __restrict__ Wg,
                            const float* __restrict__ bg) {
    int t = blockIdx.x;
    int tid = threadIdx.x;
    int e = tid & 15;
    int c = tid >> 4;
    __shared__ float part[8][17];
    __shared__ float sc[16];

    const float* xr = x + (size_t)t * DIM;
    const float* wc = Wg + e;
    float s = 0.f;
    int d0 = c * 128;
#pragma unroll 4
    for (int d = 0; d < 128; d++)
        s = fmaf(xr[d0 + d], wc[(size_t)(d0 + d) * NEXP], s);
    part[c][e] = s;
    __syncthreads();

    if (tid < 16) {
        float v = bg[tid];
#pragma unroll
        for (int cc = 0; cc < 8; cc++) v += part[cc][tid];
        sc[tid] = v;
    }
    __syncthreads();

    if (tid == 0) {
        int i1 = 0; float v1 = sc[0];
#pragma unroll
        for (int j = 1; j < 16; j++) if (sc[j] > v1) { v1 = sc[j]; i1 = j; }
        int i2 = -1; float v2 = -3.0e38f;
#pragma unroll
        for (int j = 0; j < 16; j++) if (j != i1 && sc[j] > v2) { v2 = sc[j]; i2 = j; }
        float r  = expf(v2 - v1);
        float w1 = 1.f / (1.f + r);
        float w2 = r   / (1.f + r);
        int p1 = atomicAdd(&g_cnt[i1], 1);
        g_rows[i1][p1] = 2 * t;     g_wt[i1][p1] = w1;
        int p2 = atomicAdd(&g_cnt[i2], 1);
        g_rows[i2][p2] = 2 * t + 1; g_wt[i2][p2] = w2;
    }
}

// =======================================================================
// up GEMM: out[hr] = gather(x) @ W + bias   (MODE 0: store z fp32;
//          MODE 1: read z1, h = silu(z1)*z3 -> packed Hh/Hl)
// TM=64, TN=128, TKC=16, double-buffered, one sync per chunk.
// =======================================================================
template<int MODE>
__global__ __launch_bounds__(256, 2)
void up_gemm_kernel(const float* __restrict__ x,
                    const float* __restrict__ W,      // [E][DIM][INTER]
                    const float* __restrict__ bias) { // [E][INTER]
    int e = blockIdx.z;
    int cnt = g_cnt[e];
    int m0 = blockIdx.y * TM;
    if (m0 >= cnt) return;
    int n0 = blockIdx.x * TN;

    __shared__ __align__(16) uint32_t sAh[2][TM*KW], sAl[2][TM*KW];
    __shared__ __align__(16) uint32_t sBh[2][TN*KW], sBl[2][TN*KW];
    __shared__ int sTokRow[TM];
    __shared__ int sOutRow[TM];

    int tid = threadIdx.x;
    int wid = tid >> 5;
    int lane = tid & 31;
    int grp = lane >> 2;
    int tig = lane & 3;
    int wm = (wid >> 2) * 32;
    int wn = (wid & 3) * 32;

    if (tid < TM) {
        int m = m0 + tid;
        if (m < cnt) { int r = g_rows[e][m]; sTokRow[tid] = r >> 1; sOutRow[tid] = r; }
        else         { sTokRow[tid] = -1;    sOutRow[tid] = -1; }
    }
    __syncthreads();

    const float* We = W + (size_t)e * DIM * INTER + n0;   // [k][n]

    int arow = tid >> 2, aq = tid & 3;
    int myTok = sTokRow[arow];
    const float* aptr = (myTok >= 0) ? (x + (size_t)myTok * DIM + aq * 4) : x;
    int bn = tid & 127;
    int bkg = (tid >> 7) * 8;

    float4 rA;
    float rB[8];
    const float4 zf4 = make_float4(0.f, 0.f, 0.f, 0.f);

    auto fetch = [&](int k0) {    // k0 = element offset (multiple of TKC)
        rA = (myTok >= 0) ? *reinterpret_cast<const float4*>(aptr + k0) : zf4;
#pragma unroll
        for (int j = 0; j < 8; j++)
            rB[j] = We[(size_t)(k0 + bkg + j) * INTER + bn];
    };
    auto stage = [&](int buf) {
        uint32_t h0, l0, h1, l1;
        f2bf_pair(rA.x, rA.y, h0, l0);
        f2bf_pair(rA.z, rA.w, h1, l1);
        int ab = arow * KW + aq * 2;
        *reinterpret_cast<uint2*>(&sAh[buf][ab]) = make_uint2(h0, h1);
        *reinterpret_cast<uint2*>(&sAl[buf][ab]) = make_uint2(l0, l1);
        int bb = bn * KW + (bkg >> 1);
        uint32_t bh[4], bl[4];
#pragma unroll
        for (int j = 0; j < 4; j++) f2bf_pair(rB[2*j], rB[2*j+1], bh[j], bl[j]);
        *reinterpret_cast<uint4*>(&sBh[buf][bb]) = make_uint4(bh[0], bh[1], bh[2], bh[3]);
        *reinterpret_cast<uint4*>(&sBl[buf][bb]) = make_uint4(bl[0], bl[1], bl[2], bl[3]);
    };

    float acc[2][4][4];
#pragma unroll
    for (int mt = 0; mt < 2; mt++)
#pragma unroll
        for (int nt = 0; nt < 4; nt++)
#pragma unroll
            for (int j = 0; j < 4; j++) acc[mt][nt][j] = 0.f;

    const int NC = DIM / TKC;   // 64
    fetch(0); stage(0);
    __syncthreads();
    fetch(TKC);                 // FIXED: element offset, not chunk index

    for (int c = 0; c < NC; c++) {
        int cb = c & 1;
        if (c + 1 < NC) stage((c + 1) & 1);
        if (c + 2 < NC) fetch((c + 2) * TKC);   // FIXED: element offset

        uint32_t ah[2][4], al[2][4];
#pragma unroll
        for (int mt = 0; mt < 2; mt++) {
            int r0 = (wm + mt * 16 + grp) * KW;
            int r1 = r0 + 8 * KW;
            ah[mt][0] = sAh[cb][r0 + tig];     ah[mt][1] = sAh[cb][r1 + tig];
            ah[mt][2] = sAh[cb][r0 + tig + 4]; ah[mt][3] = sAh[cb][r1 + tig + 4];
            al[mt][0] = sAl[cb][r0 + tig];     al[mt][1] = sAl[cb][r1 + tig];
            al[mt][2] = sAl[cb][r0 + tig + 4]; al[mt][3] = sAl[cb][r1 + tig + 4];
        }
#pragma unroll
        for (int nt = 0; nt < 4; nt++) {
            int nb = (wn + nt * 8 + grp) * KW;
            uint32_t bh0 = sBh[cb][nb + tig], bh1 = sBh[cb][nb + tig + 4];
            uint32_t bl0 = sBl[cb][nb + tig], bl1 = sBl[cb][nb + tig + 4];
#pragma unroll
            for (int mt = 0; mt < 2; mt++) {
                MMA16816(acc[mt][nt], ah[mt], bh0, bh1);
                MMA16816(acc[mt][nt], ah[mt], bl0, bl1);
                MMA16816(acc[mt][nt], al[mt], bh0, bh1);
            }
        }
        __syncthreads();
    }

    const float* pb = bias + (size_t)e * INTER + n0;
#pragma unroll
    for (int mt = 0; mt < 2; mt++) {
#pragma unroll
        for (int half = 0; half < 2; half++) {
            int rloc = wm + mt * 16 + grp + half * 8;
            int hr = sOutRow[rloc];
            if (hr < 0) continue;
#pragma unroll
            for (int nt = 0; nt < 4; nt++) {
                int col = wn + nt * 8 + tig * 2;
                float za = acc[mt][nt][half * 2]     + pb[col];
                float zb = acc[mt][nt][half * 2 + 1] + pb[col + 1];
                if (MODE == 0) {
                    float2 zv; zv.x = za; zv.y = zb;
                    *reinterpret_cast<float2*>(g_Z1 + (size_t)hr * INTER + n0 + col) = zv;
                } else {
                    float2 z1 = *reinterpret_cast<const float2*>(
                        g_Z1 + (size_t)hr * INTER + n0 + col);
                    float ha = (z1.x / (1.f + expf(-z1.x))) * za;
                    float hb = (z1.y / (1.f + expf(-z1.y))) * zb;
                    uint32_t hp, lp;
                    f2bf_pair(ha, hb, hp, lp);
                    g_Hh[(size_t)hr * (INTER/2) + (n0 + col)/2] = hp;
                    g_Hl[(size_t)hr * (INTER/2) + (n0 + col)/2] = lp;
                }
            }
        }
    }
}

// =======================================================================
// down GEMM: y[tok] += w * (gather(H) @ W2 + b2); packed-A, double-buffered
// =======================================================================
__global__ __launch_bounds__(256, 2)
void down_kernel(const float* __restrict__ W2, const float* __restrict__ b2,
                 float* __restrict__ y) {
    int e = blockIdx.z;
    int cnt = g_cnt[e];
    int m0 = blockIdx.y * TM;
    if (m0 >= cnt) return;
    int n0 = blockIdx.x * TN;

    __shared__ __align__(16) uint32_t sAh[2][TM*KW], sAl[2][TM*KW];
    __shared__ __align__(16) uint32_t sBh[2][TN*KW], sBl[2][TN*KW];
    __shared__ int   sHRow[TM];
    __shared__ int   sTok[TM];
    __shared__ float sW[TM];

    int tid = threadIdx.x;
    int wid = tid >> 5;
    int lane = tid & 31;
    int grp = lane >> 2;
    int tig = lane & 3;
    int wm = (wid >> 2) * 32;
    int wn = (wid & 3) * 32;

    if (tid < TM) {
        int m = m0 + tid;
        if (m < cnt) {
            int r = g_rows[e][m];
            sHRow[tid] = r; sTok[tid] = r >> 1; sW[tid] = g_wt[e][m];
        } else { sHRow[tid] = -1; sTok[tid] = -1; sW[tid] = 0.f; }
    }
    __syncthreads();

    const float* W2e = W2 + (size_t)e * INTER * DIM + n0;   // [k][n]

    int arow = tid >> 2, aq = tid & 3;
    int myH = sHRow[arow];
    const uint2* pAh = reinterpret_cast<const uint2*>(
        g_Hh + (size_t)(myH < 0 ? 0 : myH) * (INTER/2));
    const uint2* pAl = reinterpret_cast<const uint2*>(
        g_Hl + (size_t)(myH < 0 ? 0 : myH) * (INTER/2));
    int bn = tid & 127;
    int bkg = (tid >> 7) * 8;

    uint2 rAh, rAl;
    float rB[8];
    const uint2 zu2 = make_uint2(0, 0);

    auto fetch = [&](int k0) {    // k0 = element offset
        int ui = (k0 >> 2) + aq;  // uint2 index within row
        rAh = (myH >= 0) ? pAh[ui] : zu2;
        rAl = (myH >= 0) ? pAl[ui] : zu2;
#pragma unroll
        for (int j = 0; j < 8; j++)
            rB[j] = W2e[(size_t)(k0 + bkg + j) * DIM + bn];
    };
    auto stage = [&](int buf) {
        int ab = arow * KW + aq * 2;
        *reinterpret_cast<uint2*>(&sAh[buf][ab]) = rAh;
        *reinterpret_cast<uint2*>(&sAl[buf][ab]) = rAl;
        int bb = bn * KW + (bkg >> 1);
        uint32_t bh[4], bl[4];
#pragma unroll
        for (int j = 0; j < 4; j++) f2bf_pair(rB[2*j], rB[2*j+1], bh[j], bl[j]);
        *reinterpret_cast<uint4*>(&sBh[buf][bb]) = make_uint4(bh[0], bh[1], bh[2], bh[3]);
        *reinterpret_cast<uint4*>(&sBl[buf][bb]) = make_uint4(bl[0], bl[1], bl[2], bl[3]);
    };

    float acc[2][4][4];
#pragma unroll
    for (int mt = 0; mt < 2; mt++)
#pragma unroll
        for (int nt = 0; nt < 4; nt++)
#pragma unroll
            for (int j = 0; j < 4; j++) acc[mt][nt][j] = 0.f;

    const int NC = INTER / TKC;   // 128
    fetch(0); stage(0);
    __syncthreads();
    fetch(TKC);

    for (int c = 0; c < NC; c++) {
        int cb = c & 1;
        if (c + 1 < NC) stage((c + 1) & 1);
        if (c + 2 < NC) fetch((c + 2) * TKC);

        uint32_t ah[2][4], al[2][4];
#pragma unroll
        for (int mt = 0; mt < 2; mt++) {
            int r0 = (wm + mt * 16 + grp) * KW;
            int r1 = r0 + 8 * KW;
            ah[mt][0] = sAh[cb][r0 + tig];     ah[mt][1] = sAh[cb][r1 + tig];
            ah[mt][2] = sAh[cb][r0 + tig + 4]; ah[mt][3] = sAh[cb][r1 + tig + 4];
            al[mt][0] = sAl[cb][r0 + tig];     al[mt][1] = sAl[cb][r1 + tig];
            al[mt][2] = sAl[cb][r0 + tig + 4]; al[mt][3] = sAl[cb][r1 + tig + 4];
        }
#pragma unroll
        for (int nt = 0; nt < 4; nt++) {
            int nb = (wn + nt * 8 + grp) * KW;
            uint32_t bh0 = sBh[cb][nb + tig], bh1 = sBh[cb][nb + tig + 4];
            uint32_t bl0 = sBl[cb][nb + tig], bl1 = sBl[cb][nb + tig + 4];
#pragma unroll
            for (int mt = 0; mt < 2; mt++) {
                MMA16816(acc[mt][nt], ah[mt], bh0, bh1);
                MMA16816(acc[mt][nt], ah[mt], bl0, bl1);
                MMA16816(acc[mt][nt], al[mt], bh0, bh1);
            }
        }
        __syncthreads();
    }

    const float* pb2 = b2 + (size_t)e * DIM + n0;
#pragma unroll
    for (int mt = 0; mt < 2; mt++) {
#pragma unroll
        for (int half = 0; half < 2; half++) {
            int rloc = wm + mt * 16 + grp + half * 8;
            int tok = sTok[rloc];
            if (tok < 0) continue;
            float w = sW[rloc];
            float* yr = y + (size_t)tok * DIM + n0;
#pragma unroll
            for (int nt = 0; nt < 4; nt++) {
                int col = wn + nt * 8 + tig * 2;
                atomicAdd(yr + col,     (acc[mt][nt][half * 2]     + pb2[col])     * w);
                atomicAdd(yr + col + 1, (acc[mt][nt][half * 2 + 1] + pb2[col + 1]) * w);
            }
        }
    }
}

// -------------------------------- launcher --------------------------------------
extern "C" void kernel_launch(void* const* d_in, const int* in_sizes, int n_in,
                              void* d_out, int out_size) {
    const float* x  = (const float*)d_in[0];
    const float* Wg = (const float*)d_in[1];
    const float* bg = (const float*)d_in[2];
    const float* W1 = (const float*)d_in[3];
    const float* b1 = (const float*)d_in[4];
    const float* W2 = (const float*)d_in[5];
    const float* b2 = (const float*)d_in[6];
    const float* W3 = (const float*)d_in[7];
    const float* b3 = (const float*)d_in[8];
    float* y = (float*)d_out;

    zero_kernel<<<(T_TOK * DIM / 4 + 255) / 256, 256>>>(y);
    gate_kernel<<<T_TOK, 128>>>(x, Wg, bg);

    dim3 upGrid(INTER / TN, T_TOK / TM, NEXP);
    up_gemm_kernel<0><<<upGrid, 256>>>(x, W1, b1);
    up_gemm_kernel<1><<<upGrid, 256>>>(x, W3, b3);

    dim3 dnGrid(DIM / TN, T_TOK / TM, NEXP);
    down_kernel<<<dnGrid, 256>>>(W2, b2, y);
}